// round 12
// baseline (speedup 1.0000x reference)
#include <cuda_runtime.h>
#include <cuda_fp16.h>
#include <math.h>

#define NN 100000
#define NE 1200000
#define NG 512
#define MAXD 64

// -------- scratch (device globals; no allocation) --------
static __device__ __half2 g_xh [NN * 32];   // fp16 x*ns (conv1 input)
static __device__ __half2 g_h1h[NN * 32];   // fp16 h1*ns (conv2 input)
static __device__ float   g_agg[NN * 64];   // gather output (fp32)
static __device__ float   g_h2 [NN * 64];   // conv2 output (fp32, for pooling)
static __device__ int     g_dego[NN];
static __device__ int     g_degi[NN];
static __device__ int     g_ebuf[NN * MAXD]; // fixed-stride dst buckets of src ids

// -------- init --------
__global__ void k_zero() {
    int i = blockIdx.x * blockDim.x + threadIdx.x;
    if (i < NN) { g_dego[i] = 0; g_degi[i] = 0; }
}

// -------- fused degrees + bucket fill (one edge pass) --------
__global__ void k_degfill(const int4* __restrict__ src4, const int4* __restrict__ dst4) {
    int i = blockIdx.x * blockDim.x + threadIdx.x;
    if (i < NE / 4) {
        int4 s = __ldg(&src4[i]);
        int4 d = __ldg(&dst4[i]);
        atomicAdd(&g_dego[s.x], 1); atomicAdd(&g_dego[s.y], 1);
        atomicAdd(&g_dego[s.z], 1); atomicAdd(&g_dego[s.w], 1);
        int p0 = atomicAdd(&g_degi[d.x], 1); g_ebuf[d.x * MAXD + p0] = s.x;
        int p1 = atomicAdd(&g_degi[d.y], 1); g_ebuf[d.y * MAXD + p1] = s.y;
        int p2 = atomicAdd(&g_degi[d.z], 1); g_ebuf[d.z * MAXD + p2] = s.z;
        int p3 = atomicAdd(&g_degi[d.w], 1); g_ebuf[d.w * MAXD + p3] = s.w;
    }
}

// -------- prep: g_xh = half(x * ns); ns computed from dego --------
__global__ void k_prep(const float* __restrict__ x) {
    int i = blockIdx.x * blockDim.x + threadIdx.x;   // over NN*16 float4s
    if (i < NN * 16) {
        float4 v = __ldg(&((const float4*)x)[i]);
        int dov = __ldg(&g_dego[i >> 4]); if (dov < 1) dov = 1;
        float s = rsqrtf((float)dov);
        g_xh[i * 2]     = __floats2half2_rn(v.x * s, v.y * s);
        g_xh[i * 2 + 1] = __floats2half2_rn(v.z * s, v.w * s);
    }
}

#define H2REF(x) (*reinterpret_cast<const __half2*>(&(x)))

// -------- gather: 1 warp/node; 2 edges per warp-LDG.64 --------
// Half-warp h (lane>>4) owns edge e0+h of each load pair; lane&15 owns 4
// feature columns (uint2 = 2 half2). One shfl with per-lane srcLane feeds both
// halves. 4-edge fp16 tree -> fp32 accumulate. Cross-half combine at end.
__global__ void __launch_bounds__(256) k_gather(const uint2* __restrict__ xin) {
    int gw = (blockIdx.x * blockDim.x + threadIdx.x) >> 5;
    if (gw >= NN) return;
    int lane = threadIdx.x & 31;
    int hf   = lane >> 4;    // 0 or 1
    int l16  = lane & 15;

    int deg = __ldg(&g_degi[gw]);
    const int* bucket = &g_ebuf[gw * MAXD];

    // prefetch edge indices into registers (beyond-deg entries never dereferenced)
    int sidx0 = __ldg(&bucket[lane]);
    int sidx1 = (deg > 32) ? __ldg(&bucket[32 + lane]) : 0;

    float ax0 = 0.f, ay0 = 0.f, ax1 = 0.f, ay1 = 0.f;
    #pragma unroll 1
    for (int e0 = 0; e0 < deg; e0 += 4) {
        int sv = (e0 < 32) ? sidx0 : sidx1;              // uniform per batch (4 | 32)
        int sA = __shfl_sync(0xffffffffu, sv, e0 + hf);        // edges e0, e0+1
        int sB = __shfl_sync(0xffffffffu, sv, e0 + 2 + hf);    // edges e0+2, e0+3
        uint2 uA = (e0 + hf     < deg) ? __ldg(&xin[sA * 16 + l16]) : make_uint2(0u, 0u);
        uint2 uB = (e0 + 2 + hf < deg) ? __ldg(&xin[sB * 16 + l16]) : make_uint2(0u, 0u);
        __half2 t0 = __hadd2(H2REF(uA.x), H2REF(uB.x));
        __half2 t1 = __hadd2(H2REF(uA.y), H2REF(uB.y));
        float2 f0 = __half22float2(t0);
        float2 f1 = __half22float2(t1);
        ax0 += f0.x; ay0 += f0.y;
        ax1 += f1.x; ay1 += f1.y;
    }

    // combine the two half-warps (each holds same 4 columns for its edges)
    ax0 += __shfl_xor_sync(0xffffffffu, ax0, 16);
    ay0 += __shfl_xor_sync(0xffffffffu, ay0, 16);
    ax1 += __shfl_xor_sync(0xffffffffu, ax1, 16);
    ay1 += __shfl_xor_sync(0xffffffffu, ay1, 16);

    if (hf == 0) {
        int div_ = deg; if (div_ < 1) div_ = 1;
        float ndv = rsqrtf((float)div_);
        ((float4*)g_agg)[gw * 16 + l16] =
            make_float4(ax0 * ndv, ay0 * ndv, ax1 * ndv, ay1 * ndv);
    }
}

// -------- tiled GEMM [64-tile,64] @ W[64,64] + b, LN, ReLU --------
// k unrolled x4: X row segments loaded as float4 (4 LDS.128 + 4 LDS.128 per 4k).
__global__ void __launch_bounds__(256) k_gemm(
        int last,
        const float* __restrict__ W, const float* __restrict__ b,
        const float* __restrict__ gm, const float* __restrict__ bt) {
    __shared__ float Xs[64 * 64];
    __shared__ float Ws[64 * 64];

    int tid = threadIdx.x;
    int base = blockIdx.x * 64;

    const float4* agg4 = (const float4*)g_agg;
    const float4* W4 = (const float4*)W;
    #pragma unroll
    for (int i = 0; i < 4; i++) {
        int idx = tid + i * 256;            // over 1024 float4s
        int row = base + (idx >> 4);
        ((float4*)Xs)[idx] = (row < NN) ? __ldg(&agg4[row * 16 + (idx & 15)])
                                        : make_float4(0.f, 0.f, 0.f, 0.f);
        ((float4*)Ws)[idx] = __ldg(&W4[idx]);
    }
    __syncthreads();

    int R = tid >> 4;
    int C = tid & 15;

    float acc[4][4];
    #pragma unroll
    for (int r = 0; r < 4; r++)
        #pragma unroll
        for (int c = 0; c < 4; c++) acc[r][c] = 0.f;

    const float4* Xv = (const float4*)Xs;
    const float4* Wv = (const float4*)Ws;

    #pragma unroll 4
    for (int k4 = 0; k4 < 16; k4++) {
        float4 xr0 = Xv[(R * 4 + 0) * 16 + k4];
        float4 xr1 = Xv[(R * 4 + 1) * 16 + k4];
        float4 xr2 = Xv[(R * 4 + 2) * 16 + k4];
        float4 xr3 = Xv[(R * 4 + 3) * 16 + k4];
        float4 b0 = Wv[(k4 * 4 + 0) * 16 + C];
        float4 b1 = Wv[(k4 * 4 + 1) * 16 + C];
        float4 b2 = Wv[(k4 * 4 + 2) * 16 + C];
        float4 b3 = Wv[(k4 * 4 + 3) * 16 + C];
        #define GSTEP(xf, bv) \
            acc[0][0] += xr0.xf * bv.x; acc[0][1] += xr0.xf * bv.y; \
            acc[0][2] += xr0.xf * bv.z; acc[0][3] += xr0.xf * bv.w; \
            acc[1][0] += xr1.xf * bv.x; acc[1][1] += xr1.xf * bv.y; \
            acc[1][2] += xr1.xf * bv.z; acc[1][3] += xr1.xf * bv.w; \
            acc[2][0] += xr2.xf * bv.x; acc[2][1] += xr2.xf * bv.y; \
            acc[2][2] += xr2.xf * bv.z; acc[2][3] += xr2.xf * bv.w; \
            acc[3][0] += xr3.xf * bv.x; acc[3][1] += xr3.xf * bv.y; \
            acc[3][2] += xr3.xf * bv.z; acc[3][3] += xr3.xf * bv.w;
        GSTEP(x, b0)
        GSTEP(y, b1)
        GSTEP(z, b2)
        GSTEP(w, b3)
        #undef GSTEP
    }

    float4 bias = ((const float4*)b)[C];
    float4 gmv  = ((const float4*)gm)[C];
    float4 btv  = ((const float4*)bt)[C];

    #pragma unroll
    for (int r = 0; r < 4; r++) {
        int row = base + R * 4 + r;
        float o0 = acc[r][0] + bias.x;
        float o1 = acc[r][1] + bias.y;
        float o2 = acc[r][2] + bias.z;
        float o3 = acc[r][3] + bias.w;
        float s = o0 + o1 + o2 + o3;
        #pragma unroll
        for (int m = 1; m < 16; m <<= 1) s += __shfl_xor_sync(0xffffffffu, s, m);
        float mean = s * (1.f / 64.f);
        float d0 = o0 - mean, d1 = o1 - mean, d2 = o2 - mean, d3 = o3 - mean;
        float vv = d0 * d0 + d1 * d1 + d2 * d2 + d3 * d3;
        #pragma unroll
        for (int m = 1; m < 16; m <<= 1) vv += __shfl_xor_sync(0xffffffffu, vv, m);
        float inv = rsqrtf(vv * (1.f / 64.f) + 1e-5f);
        float y0 = fmaxf(d0 * inv * gmv.x + btv.x, 0.f);
        float y1 = fmaxf(d1 * inv * gmv.y + btv.y, 0.f);
        float y2 = fmaxf(d2 * inv * gmv.z + btv.z, 0.f);
        float y3 = fmaxf(d3 * inv * gmv.w + btv.w, 0.f);
        if (row < NN) {
            if (last) {
                ((float4*)g_h2)[row * 16 + C] = make_float4(y0, y1, y2, y3);
            } else {
                int dov = __ldg(&g_dego[row]); if (dov < 1) dov = 1;
                float nsr = rsqrtf((float)dov);
                g_h1h[row * 32 + C * 2]     = __floats2half2_rn(y0 * nsr, y1 * nsr);
                g_h1h[row * 32 + C * 2 + 1] = __floats2half2_rn(y2 * nsr, y3 * nsr);
            }
        }
    }
}

// -------- fused pooling + classifier head: one block (256 threads) per graph ----
__global__ void __launch_bounds__(256) k_poolcls(
        const int* __restrict__ gid,
        const float* __restrict__ Wc1, const float* __restrict__ bc1,
        const float* __restrict__ g3,  const float* __restrict__ be3,
        const float* __restrict__ Wc2, const float* __restrict__ bc2,
        const float* __restrict__ g4,  const float* __restrict__ be4,
        const float* __restrict__ Wc3, const float* __restrict__ bc3,
        float* __restrict__ out) {
    __shared__ float ss[256], mm[256];
    __shared__ float hA[64], hB[64], o1s[64], red[64];
    int g = blockIdx.x, t = threadIdx.x;
    int col = t & 63, chunk = t >> 6;

    int lo = 0, hi = NN;
    while (lo < hi) { int mid = (lo + hi) >> 1; if (__ldg(&gid[mid]) < g)     lo = mid + 1; else hi = mid; }
    int start = lo;
    lo = start; hi = NN;
    while (lo < hi) { int mid = (lo + hi) >> 1; if (__ldg(&gid[mid]) < g + 1) lo = mid + 1; else hi = mid; }
    int end = lo;

    float s = 0.f, m = 0.f;   // post-ReLU >= 0
    for (int n = start + chunk; n < end; n += 4) {
        float v = g_h2[n * 64 + col];
        s += v;
        m = fmaxf(m, v);
    }
    ss[t] = s; mm[t] = m;
    __syncthreads();

    float mv = 0.f, xv = 0.f;
    if (t < 64) {
        float cnt = (float)(end - start); if (cnt < 1.f) cnt = 1.f;
        mv = (ss[t] + ss[64 + t] + ss[128 + t] + ss[192 + t]) / cnt;
        xv = fmaxf(fmaxf(mm[t], mm[64 + t]), fmaxf(mm[128 + t], mm[192 + t]));
    }

    if (t < 64) red[t] = mv * mv;
    __syncthreads();
    for (int o = 32; o; o >>= 1) { if (t < o) red[t] += red[t + o]; __syncthreads(); }
    float nA = fmaxf(sqrtf(red[0]), 1e-12f); __syncthreads();
    if (t < 64) red[t] = xv * xv;
    __syncthreads();
    for (int o = 32; o; o >>= 1) { if (t < o) red[t] += red[t + o]; __syncthreads(); }
    float nB = fmaxf(sqrtf(red[0]), 1e-12f); __syncthreads();

    if (t < 64) { hA[t] = mv / nA; hB[t] = xv / nB; }
    __syncthreads();

    float acc = 0.f;
    if (t < 64) {
        acc = bc1[t];
        #pragma unroll 4
        for (int k = 0; k < 64; k++) acc += hA[k] * Wc1[k * 64 + t];
        #pragma unroll 4
        for (int k = 0; k < 64; k++) acc += hB[k] * Wc1[(64 + k) * 64 + t];
        red[t] = acc;
    }
    __syncthreads();
    for (int o = 32; o; o >>= 1) { if (t < o) red[t] += red[t + o]; __syncthreads(); }
    float mean = red[0] * (1.f / 64.f); __syncthreads();
    float dv = acc - mean;
    if (t < 64) red[t] = dv * dv;
    __syncthreads();
    for (int o = 32; o; o >>= 1) { if (t < o) red[t] += red[t + o]; __syncthreads(); }
    float inv = rsqrtf(red[0] * (1.f / 64.f) + 1e-5f); __syncthreads();
    if (t < 64) o1s[t] = fmaxf(dv * inv * g3[t] + be3[t], 0.f);
    __syncthreads();

    if (t < 64) {
        acc = bc2[t];
        #pragma unroll 4
        for (int k = 0; k < 64; k++) acc += o1s[k] * Wc2[k * 64 + t];
        red[t] = acc;
    }
    __syncthreads();
    for (int o = 32; o; o >>= 1) { if (t < o) red[t] += red[t + o]; __syncthreads(); }
    mean = red[0] * (1.f / 64.f); __syncthreads();
    dv = acc - mean;
    if (t < 64) red[t] = dv * dv;
    __syncthreads();
    for (int o = 32; o; o >>= 1) { if (t < o) red[t] += red[t + o]; __syncthreads(); }
    inv = rsqrtf(red[0] * (1.f / 64.f) + 1e-5f); __syncthreads();
    float o2 = fmaxf(dv * inv * g4[t < 64 ? t : 0] + be4[t < 64 ? t : 0], 0.f);

    if (t < 64) red[t] = o2 * Wc3[t];
    __syncthreads();
    for (int o = 32; o; o >>= 1) { if (t < o) red[t] += red[t + o]; __syncthreads(); }
    if (t == 0) out[g] = red[0] + bc3[0];
}

extern "C" void kernel_launch(void* const* d_in, const int* in_sizes, int n_in,
                              void* d_out, int out_size) {
    const float* h   = (const float*)d_in[0];
    const int*   src = (const int*)  d_in[1];
    const int*   dst = (const int*)  d_in[2];
    const int*   gid = (const int*)  d_in[3];
    const float* W1  = (const float*)d_in[4];
    const float* b1  = (const float*)d_in[5];
    const float* W2  = (const float*)d_in[6];
    const float* b2  = (const float*)d_in[7];
    const float* g1  = (const float*)d_in[8];
    const float* be1 = (const float*)d_in[9];
    const float* g2  = (const float*)d_in[10];
    const float* be2 = (const float*)d_in[11];
    const float* g3  = (const float*)d_in[12];
    const float* be3 = (const float*)d_in[13];
    const float* g4  = (const float*)d_in[14];
    const float* be4 = (const float*)d_in[15];
    const float* Wc1 = (const float*)d_in[16];
    const float* bc1 = (const float*)d_in[17];
    const float* Wc2 = (const float*)d_in[18];
    const float* bc2 = (const float*)d_in[19];
    const float* Wc3 = (const float*)d_in[20];
    const float* bc3 = (const float*)d_in[21];
    float* out = (float*)d_out;

    uint2* xh = nullptr; uint2* h1h = nullptr;
    cudaGetSymbolAddress((void**)&xh,  g_xh);
    cudaGetSymbolAddress((void**)&h1h, g_h1h);

    k_zero   <<<(NN + 255) / 256, 256>>>();
    k_degfill<<<(NE / 4 + 255) / 256, 256>>>((const int4*)src, (const int4*)dst);
    k_prep   <<<(NN * 16 + 255) / 256, 256>>>(h);

    k_gather<<<(NN * 32 + 255) / 256, 256>>>(xh);
    k_gemm  <<<(NN + 63) / 64, 256>>>(0, W1, b1, g1, be1);
    k_gather<<<(NN * 32 + 255) / 256, 256>>>(h1h);
    k_gemm  <<<(NN + 63) / 64, 256>>>(1, W2, b2, g2, be2);

    k_poolcls<<<NG, 256>>>(gid, Wc1, bc1, g3, be3, Wc2, bc2, g4, be4, Wc3, bc3, out);
}